// round 7
// baseline (speedup 1.0000x reference)
#include <cuda_runtime.h>
#include <cstdint>
#include <math.h>

// Problem constants
#define BDIM 4
#define SDIM 2048
#define DDIM 2048
#define HDIM 16
#define DKDIM 128
#define MDIM (BDIM * SDIM)   // 8192
#define GK 2048
#define GN 2048

#define NEGV (-1e9f)
#define SCALE 0.08838834764831845f  // 1/sqrt(128)

// u32 offset of the "lo" plane inside a split tensor (hi plane first)
#define LOOFF ((size_t)MDIM * 1024)

// Scratch (device globals — no cudaMalloc allowed)
__device__ float g_Q[(size_t)MDIM * DDIM];   // split Q: hi[8192][1024] | lo[8192][1024] (u32)
__device__ float g_K[(size_t)MDIM * DDIM];   // split K: same layout
__device__ float g_V[(size_t)MDIM * DDIM];   // fp32 V
__device__ float g_att[(size_t)MDIM * DDIM];
__device__ float g_vmean[BDIM * HDIM * DKDIM];

// ---------------------------------------------------------------------------
// Helpers
// ---------------------------------------------------------------------------
__device__ __forceinline__ void mma_bf16_16x8x16(
    float* c, const uint32_t* a, uint32_t b0, uint32_t b1)
{
    asm volatile(
        "mma.sync.aligned.m16n8k16.row.col.f32.bf16.bf16.f32 "
        "{%0,%1,%2,%3}, {%4,%5,%6,%7}, {%8,%9}, {%0,%1,%2,%3};"
        : "+f"(c[0]), "+f"(c[1]), "+f"(c[2]), "+f"(c[3])
        : "r"(a[0]), "r"(a[1]), "r"(a[2]), "r"(a[3]), "r"(b0), "r"(b1));
}

// Split a pair of fp32 into packed bf16 hi and packed bf16 lo (rn-even).
__device__ __forceinline__ void split2(float x, float y, uint32_t& hi, uint32_t& lo)
{
    uint32_t bx = __float_as_uint(x), by = __float_as_uint(y);
    uint32_t hx = (bx + 0x7FFFu + ((bx >> 16) & 1u)) >> 16;
    uint32_t hy = (by + 0x7FFFu + ((by >> 16) & 1u)) >> 16;
    hi = hx | (hy << 16);
    float lx = x - __uint_as_float(hx << 16);
    float ly = y - __uint_as_float(hy << 16);
    uint32_t blx = __float_as_uint(lx), bly = __float_as_uint(ly);
    uint32_t hlx = (blx + 0x7FFFu + ((blx >> 16) & 1u)) >> 16;
    uint32_t hly = (bly + 0x7FFFu + ((bly >> 16) & 1u)) >> 16;
    lo = hlx | (hly << 16);
}

// Fast exp on FMA pipe. Rel err ~2e-6 for x <= 0.
__device__ __forceinline__ float fexp(float x)
{
    float t = x * 1.4426950408889634f;
    t = fmaxf(t, -126.0f);
    float n = rintf(t);
    float f = t - n;
    float p = 0.0013333558f;
    p = fmaf(p, f, 0.0096181291f);
    p = fmaf(p, f, 0.0555041087f);
    p = fmaf(p, f, 0.2402265070f);
    p = fmaf(p, f, 0.6931471806f);
    p = fmaf(p, f, 1.0f);
    int e = (int)n;
    return __uint_as_float((uint32_t)((e + 127) << 23)) * p;
}

// ===========================================================================
// GEMM (TN) via split-bf16 mma: C = A @ W.T.
// mode 0: fp32 output.  mode 1: split hi/lo u32 d-paired output.
// ===========================================================================
__global__ void __launch_bounds__(256, 2) gemm_mma_kernel(
    const float* __restrict__ A, const float* __restrict__ W, void* __restrict__ Cv,
    int mode)
{
    __shared__ uint32_t Ahs[128][20];
    __shared__ uint32_t Als[128][20];
    __shared__ uint32_t Bhs[128][20];
    __shared__ uint32_t Bls[128][20];

    const int tid  = threadIdx.x;
    const int lane = tid & 31;
    const int w    = tid >> 5;
    const int wm   = (w & 3) * 32;
    const int wn   = (w >> 2) * 64;
    const int gid  = lane >> 2;
    const int tig  = lane & 3;
    const int bm   = blockIdx.y * 128;
    const int bn   = blockIdx.x * 128;

    const int r0   = tid >> 3;
    const int c0f  = (tid & 7) * 4;
    const int c0u  = (tid & 7) * 2;

    const float* Ap = A + (size_t)(bm + r0) * GK + c0f;
    const float* Wp = W + (size_t)(bn + r0) * GK + c0f;

    float acc[2][8][4];
#pragma unroll
    for (int mt = 0; mt < 2; mt++)
#pragma unroll
        for (int nt = 0; nt < 8; nt++)
#pragma unroll
            for (int q = 0; q < 4; q++) acc[mt][nt][q] = 0.f;

    for (int kc = 0; kc < GK / 32; kc++) {
        __syncthreads();
        const float* Ak = Ap + kc * 32;
        const float* Wk = Wp + kc * 32;
#pragma unroll
        for (int j = 0; j < 4; j++) {
            float4 a = *(const float4*)(Ak + (size_t)(32 * j) * GK);
            uint32_t h0, l0, h1, l1;
            split2(a.x, a.y, h0, l0); split2(a.z, a.w, h1, l1);
            *(uint2*)&Ahs[r0 + 32 * j][c0u] = make_uint2(h0, h1);
            *(uint2*)&Als[r0 + 32 * j][c0u] = make_uint2(l0, l1);
            float4 b = *(const float4*)(Wk + (size_t)(32 * j) * GK);
            split2(b.x, b.y, h0, l0); split2(b.z, b.w, h1, l1);
            *(uint2*)&Bhs[r0 + 32 * j][c0u] = make_uint2(h0, h1);
            *(uint2*)&Bls[r0 + 32 * j][c0u] = make_uint2(l0, l1);
        }
        __syncthreads();

#pragma unroll
        for (int ks = 0; ks < 2; ks++) {
            const int kb = ks * 8;
            uint32_t ah[2][4], al[2][4];
#pragma unroll
            for (int mt = 0; mt < 2; mt++) {
                const int rb = wm + mt * 16;
                ah[mt][0] = Ahs[rb + gid][kb + tig];
                ah[mt][1] = Ahs[rb + gid + 8][kb + tig];
                ah[mt][2] = Ahs[rb + gid][kb + tig + 4];
                ah[mt][3] = Ahs[rb + gid + 8][kb + tig + 4];
                al[mt][0] = Als[rb + gid][kb + tig];
                al[mt][1] = Als[rb + gid + 8][kb + tig];
                al[mt][2] = Als[rb + gid][kb + tig + 4];
                al[mt][3] = Als[rb + gid + 8][kb + tig + 4];
            }
#pragma unroll
            for (int nt = 0; nt < 8; nt++) {
                const int nb = wn + nt * 8 + gid;
                uint32_t bh0 = Bhs[nb][kb + tig], bh1 = Bhs[nb][kb + tig + 4];
                uint32_t bl0 = Bls[nb][kb + tig], bl1 = Bls[nb][kb + tig + 4];
                mma_bf16_16x8x16(acc[0][nt], ah[0], bh0, bh1);
                mma_bf16_16x8x16(acc[1][nt], ah[1], bh0, bh1);
                mma_bf16_16x8x16(acc[0][nt], ah[0], bl0, bl1);
                mma_bf16_16x8x16(acc[1][nt], ah[1], bl0, bl1);
                mma_bf16_16x8x16(acc[0][nt], al[0], bh0, bh1);
                mma_bf16_16x8x16(acc[1][nt], al[1], bh0, bh1);
            }
        }
    }

    if (mode == 0) {
        float* C = (float*)Cv;
#pragma unroll
        for (int mt = 0; mt < 2; mt++) {
            const int row = bm + wm + mt * 16 + gid;
#pragma unroll
            for (int nt = 0; nt < 8; nt++) {
                const int col = bn + wn + nt * 8 + tig * 2;
                *(float2*)(C + (size_t)row * GN + col) =
                    make_float2(acc[mt][nt][0], acc[mt][nt][1]);
                *(float2*)(C + (size_t)(row + 8) * GN + col) =
                    make_float2(acc[mt][nt][2], acc[mt][nt][3]);
            }
        }
    } else {
        uint32_t* U = (uint32_t*)Cv;
#pragma unroll
        for (int mt = 0; mt < 2; mt++) {
            const int row = bm + wm + mt * 16 + gid;
#pragma unroll
            for (int nt = 0; nt < 8; nt++) {
                const int colp = (bn + wn + nt * 8) / 2 + tig;
                uint32_t h0, l0, h1, l1;
                split2(acc[mt][nt][0], acc[mt][nt][1], h0, l0);
                split2(acc[mt][nt][2], acc[mt][nt][3], h1, l1);
                U[(size_t)row * 1024 + colp] = h0;
                U[LOOFF + (size_t)row * 1024 + colp] = l0;
                U[(size_t)(row + 8) * 1024 + colp] = h1;
                U[LOOFF + (size_t)(row + 8) * 1024 + colp] = l1;
            }
        }
    }
}

// ---------------------------------------------------------------------------
// Per-(b,h) mean of V over sequence.
// ---------------------------------------------------------------------------
__global__ void vmean_kernel(const float* __restrict__ Vg, float* __restrict__ vmean)
{
    __shared__ float red[8][128];
    int bh = blockIdx.x;
    int b = bh >> 4, h = bh & 15;
    int d = threadIdx.x & 127;
    int ch = threadIdx.x >> 7;
    const float* Vb = Vg + ((size_t)b * SDIM + ch * 256) * DDIM + h * DKDIM + d;
    float s = 0.f;
    for (int j = 0; j < 256; j++) s += Vb[(size_t)j * DDIM];
    red[ch][d] = s;
    __syncthreads();
    if (ch == 0) {
        float t = red[0][d] + red[1][d] + red[2][d] + red[3][d]
                + red[4][d] + red[5][d] + red[6][d] + red[7][d];
        vmean[bh * DKDIM + d] = t * (1.f / (float)SDIM);
    }
}

// ===========================================================================
// Flash attention, split-bf16 3-term mma, q-tile 128, warp = 16q x 64keys.
// Softmax fully warp-local (registers). P lives in registers (C-frag == A-frag).
// Q/K arrive pre-split (hi/lo u32 d-pairs); V split in-kernel into key-pairs.
// SMEM (u32): QH[128][68] | QL | KH[64][68] | KL | VH[32][136] | VL | mask[64]
// ===========================================================================
#define AQH 0
#define AQL 8704
#define AKH 17408
#define AKL 21760
#define AVH 26112
#define AVL 30464
#define AMSK 34816
#define ATT_U32 34880
#define ATT_SMEM_BYTES (ATT_U32 * 4)   // 139520

__global__ void __launch_bounds__(256) attn_mma_kernel(
    const uint32_t* __restrict__ Qp, const uint32_t* __restrict__ Kp,
    const float* __restrict__ Vg, const int* __restrict__ maskg,
    const float* __restrict__ vmean, float* __restrict__ Og)
{
    extern __shared__ uint32_t smu[];
    int* maskS = (int*)(smu + AMSK);

    const int qt = blockIdx.x, h = blockIdx.y, b = blockIdx.z;
    const int tid = threadIdx.x, lane = tid & 31, w = tid >> 5;
    const int gid = lane >> 2, tig = lane & 3;
    const int q0 = qt * 128;
    const int r1 = w * 16 + gid, r2 = r1 + 8;

    const uint32_t* Qbase = Qp + (size_t)(b * SDIM + q0) * 1024 + h * 64;
    const uint32_t* Kbase = Kp + (size_t)(b * SDIM) * 1024 + h * 64;
    const float* Vbase = Vg + (size_t)(b * SDIM) * DDIM + h * DKDIM;
    const int* mb = maskg + b * SDIM;

    // Load Q tile (pre-split): 128 rows x 64 u32 per plane
    for (int i = tid; i < 2048; i += 256) {
        int r = i >> 4, c4 = (i & 15) * 4;
        *(uint4*)&smu[AQH + r * 68 + c4] = *(const uint4*)(Qbase + (size_t)r * 1024 + c4);
        *(uint4*)&smu[AQL + r * 68 + c4] =
            *(const uint4*)(Qbase + LOOFF + (size_t)r * 1024 + c4);
    }

    float m1 = -3.402823466e38f, m2 = -3.402823466e38f;
    float l1 = 0.f, l2 = 0.f;
    float o[16][4];
#pragma unroll
    for (int nt = 0; nt < 16; nt++)
#pragma unroll
        for (int q = 0; q < 4; q++) o[nt][q] = 0.f;

    const int nkt = 2 * qt + 2;
    for (int kt = 0; kt < nkt; kt++) {
        const int k0 = kt * 64;
        __syncthreads();  // prev-iter smem reads (and Q writes on iter 0) complete

        // K tile (pre-split): 64 rows x 64 u32 per plane  [FIXED: full row width]
        for (int i = tid; i < 1024; i += 256) {
            int r = i >> 4, c4 = (i & 15) * 4;
            *(uint4*)&smu[AKH + r * 68 + c4] =
                *(const uint4*)(Kbase + (size_t)(k0 + r) * 1024 + c4);
            *(uint4*)&smu[AKL + r * 68 + c4] =
                *(const uint4*)(Kbase + LOOFF + (size_t)(k0 + r) * 1024 + c4);
        }
        // V tile: fp32 -> key-paired split (pairs (2kp, 2kp+1)), [32 kp][128 d]
        for (int i = tid; i < 1024; i += 256) {
            int kp = i >> 5, d4 = (i & 31) * 4;
            float4 va = *(const float4*)(Vbase + (size_t)(k0 + 2 * kp) * DDIM + d4);
            float4 vb = *(const float4*)(Vbase + (size_t)(k0 + 2 * kp + 1) * DDIM + d4);
            uint32_t h0, l0, h1, l1u, h2, l2u, h3, l3;
            split2(va.x, vb.x, h0, l0); split2(va.y, vb.y, h1, l1u);
            split2(va.z, vb.z, h2, l2u); split2(va.w, vb.w, h3, l3);
            uint32_t off = (uint32_t)(kp * 136 + d4);
            *(uint4*)&smu[AVH + off] = make_uint4(h0, h1, h2, h3);
            *(uint4*)&smu[AVL + off] = make_uint4(l0, l1u, l2u, l3);
        }
        if (tid < 64) maskS[tid] = mb[k0 + tid];
        __syncthreads();

        // QK^T: 3-term split-bf16. sc[nt][q]: rows r1/r2, cols nt*8+2tig+{0,1}
        float sc[8][4];
#pragma unroll
        for (int nt = 0; nt < 8; nt++)
#pragma unroll
            for (int q = 0; q < 4; q++) sc[nt][q] = 0.f;

#pragma unroll
        for (int ks = 0; ks < 8; ks++) {
            uint32_t ah[4], al[4];
            ah[0] = smu[AQH + r1 * 68 + ks * 8 + tig];
            ah[1] = smu[AQH + r2 * 68 + ks * 8 + tig];
            ah[2] = smu[AQH + r1 * 68 + ks * 8 + 4 + tig];
            ah[3] = smu[AQH + r2 * 68 + ks * 8 + 4 + tig];
            al[0] = smu[AQL + r1 * 68 + ks * 8 + tig];
            al[1] = smu[AQL + r2 * 68 + ks * 8 + tig];
            al[2] = smu[AQL + r1 * 68 + ks * 8 + 4 + tig];
            al[3] = smu[AQL + r2 * 68 + ks * 8 + 4 + tig];
#pragma unroll
            for (int nt = 0; nt < 8; nt++) {
                const int key = nt * 8 + gid;
                uint32_t kh0 = smu[AKH + key * 68 + ks * 8 + tig];
                uint32_t kh1 = smu[AKH + key * 68 + ks * 8 + 4 + tig];
                uint32_t kl0 = smu[AKL + key * 68 + ks * 8 + tig];
                uint32_t kl1 = smu[AKL + key * 68 + ks * 8 + 4 + tig];
                mma_bf16_16x8x16(sc[nt], ah, kh0, kh1);
                mma_bf16_16x8x16(sc[nt], ah, kl0, kl1);
                mma_bf16_16x8x16(sc[nt], al, kh0, kh1);
            }
        }

        // Mask + scale + warp-local tile max
        float tm1 = -3.402823466e38f, tm2 = -3.402823466e38f;
#pragma unroll
        for (int nt = 0; nt < 8; nt++) {
#pragma unroll
            for (int jj = 0; jj < 2; jj++) {
                const int col = nt * 8 + tig * 2 + jj;
                const int jg = k0 + col;
                const bool ok = (maskS[col] != 0);
                float s0 = (ok && jg <= q0 + r1) ? sc[nt][jj] * SCALE : NEGV;
                float s1 = (ok && jg <= q0 + r2) ? sc[nt][2 + jj] * SCALE : NEGV;
                sc[nt][jj] = s0; sc[nt][2 + jj] = s1;
                tm1 = fmaxf(tm1, s0); tm2 = fmaxf(tm2, s1);
            }
        }
        tm1 = fmaxf(tm1, __shfl_xor_sync(0xffffffffu, tm1, 1));
        tm1 = fmaxf(tm1, __shfl_xor_sync(0xffffffffu, tm1, 2));
        tm2 = fmaxf(tm2, __shfl_xor_sync(0xffffffffu, tm2, 1));
        tm2 = fmaxf(tm2, __shfl_xor_sync(0xffffffffu, tm2, 2));

        const float mn1 = fmaxf(m1, tm1), mn2 = fmaxf(m2, tm2);
        const float c1 = fexp(m1 - mn1), c2 = fexp(m2 - mn2);
        m1 = mn1; m2 = mn2;

        // Exponentiate in place; accumulate partial row sums
        float s1sum = 0.f, s2sum = 0.f;
#pragma unroll
        for (int nt = 0; nt < 8; nt++) {
            sc[nt][0] = fexp(sc[nt][0] - mn1);
            sc[nt][1] = fexp(sc[nt][1] - mn1);
            sc[nt][2] = fexp(sc[nt][2] - mn2);
            sc[nt][3] = fexp(sc[nt][3] - mn2);
            s1sum += sc[nt][0] + sc[nt][1];
            s2sum += sc[nt][2] + sc[nt][3];
        }
        s1sum += __shfl_xor_sync(0xffffffffu, s1sum, 1);
        s1sum += __shfl_xor_sync(0xffffffffu, s1sum, 2);
        s2sum += __shfl_xor_sync(0xffffffffu, s2sum, 1);
        s2sum += __shfl_xor_sync(0xffffffffu, s2sum, 2);
        l1 = l1 * c1 + s1sum;
        l2 = l2 * c2 + s2sum;

        // Rescale accumulators
#pragma unroll
        for (int nt = 0; nt < 16; nt++) {
            o[nt][0] *= c1; o[nt][1] *= c1; o[nt][2] *= c2; o[nt][3] *= c2;
        }

        // PV: P C-frags map directly onto A-frags (pairs in registers)
#pragma unroll
        for (int ks2 = 0; ks2 < 4; ks2++) {
            uint32_t ph[4], pl[4];
            split2(sc[2 * ks2][0], sc[2 * ks2][1], ph[0], pl[0]);
            split2(sc[2 * ks2][2], sc[2 * ks2][3], ph[1], pl[1]);
            split2(sc[2 * ks2 + 1][0], sc[2 * ks2 + 1][1], ph[2], pl[2]);
            split2(sc[2 * ks2 + 1][2], sc[2 * ks2 + 1][3], ph[3], pl[3]);
#pragma unroll
            for (int nt = 0; nt < 16; nt++) {
                const int d = nt * 8 + gid;
                uint32_t vh0 = smu[AVH + (ks2 * 8 + tig) * 136 + d];
                uint32_t vh1 = smu[AVH + (ks2 * 8 + 4 + tig) * 136 + d];
                uint32_t vl0 = smu[AVL + (ks2 * 8 + tig) * 136 + d];
                uint32_t vl1 = smu[AVL + (ks2 * 8 + 4 + tig) * 136 + d];
                mma_bf16_16x8x16(o[nt], ph, vh0, vh1);
                mma_bf16_16x8x16(o[nt], ph, vl0, vl1);
                mma_bf16_16x8x16(o[nt], pl, vh0, vh1);
            }
        }
    }

    // Epilogue
    const float inv1 = 1.f / l1, inv2 = 1.f / l2;
    const bool dead1 = m1 < -1e8f, dead2 = m2 < -1e8f;
    const float* vm = vmean + ((size_t)b * HDIM + h) * DKDIM;
    float* O1 = Og + ((size_t)b * SDIM + q0 + r1) * DDIM + h * DKDIM;
    float* O2 = Og + ((size_t)b * SDIM + q0 + r2) * DDIM + h * DKDIM;
#pragma unroll
    for (int nt = 0; nt < 16; nt++) {
        const int d = nt * 8 + tig * 2;
        float2 u1 = dead1 ? make_float2(vm[d], vm[d + 1])
                          : make_float2(o[nt][0] * inv1, o[nt][1] * inv1);
        float2 u2 = dead2 ? make_float2(vm[d], vm[d + 1])
                          : make_float2(o[nt][2] * inv2, o[nt][3] * inv2);
        *(float2*)(O1 + d) = u1;
        *(float2*)(O2 + d) = u2;
    }
}

// ---------------------------------------------------------------------------
extern "C" void kernel_launch(void* const* d_in, const int* in_sizes, int n_in,
                              void* d_out, int out_size)
{
    const float* x    = (const float*)d_in[0];
    const int*   mask = (const int*)d_in[1];
    const float* wq   = (const float*)d_in[2];
    const float* wk   = (const float*)d_in[3];
    const float* wv   = (const float*)d_in[4];
    const float* wo   = (const float*)d_in[5];
    float* out = (float*)d_out;

    float *pQ, *pK, *pV, *pAtt, *pVm;
    cudaGetSymbolAddress((void**)&pQ, g_Q);
    cudaGetSymbolAddress((void**)&pK, g_K);
    cudaGetSymbolAddress((void**)&pV, g_V);
    cudaGetSymbolAddress((void**)&pAtt, g_att);
    cudaGetSymbolAddress((void**)&pVm, g_vmean);

    cudaFuncSetAttribute(attn_mma_kernel, cudaFuncAttributeMaxDynamicSharedMemorySize,
                         ATT_SMEM_BYTES);

    dim3 gg(GN / 128, MDIM / 128);  // (16, 64)
    gemm_mma_kernel<<<gg, 256>>>(x, wq, pQ, 1);   // split output
    gemm_mma_kernel<<<gg, 256>>>(x, wk, pK, 1);   // split output
    gemm_mma_kernel<<<gg, 256>>>(x, wv, pV, 0);   // fp32 output

    vmean_kernel<<<BDIM * HDIM, 1024>>>(pV, pVm);

    attn_mma_kernel<<<dim3(SDIM / 128, HDIM, BDIM), 256, ATT_SMEM_BYTES>>>(
        (const uint32_t*)pQ, (const uint32_t*)pK, pV, mask, pVm, pAtt);

    gemm_mma_kernel<<<gg, 256>>>(pAtt, wo, out, 0);
}

// round 8
// speedup vs baseline: 1.1530x; 1.1530x over previous
#include <cuda_runtime.h>
#include <cstdint>
#include <math.h>

// Problem constants
#define BDIM 4
#define SDIM 2048
#define DDIM 2048
#define HDIM 16
#define DKDIM 128
#define MDIM (BDIM * SDIM)   // 8192
#define GK 2048
#define GN 2048

#define NEGV (-1e9f)
#define SCALE 0.08838834764831845f  // 1/sqrt(128)

// Fragment-plane offsets
#define QLOFF 8388608ull       // u32 offset of lo plane (Q A-frag layout)
#define KLOFF 8388608ull       // u32 offset of lo plane (K B-frag layout)
#define QLOFF4 2097152ull      // same in uint4 units
#define KLOFF4 2097152ull      // K lo in uint4 units (4194304 uint2 = 2097152 uint4)

// Scratch (device globals — no cudaMalloc allowed)
__device__ float g_Q[(size_t)MDIM * DDIM];   // Q in A-frag layout: hi|lo planes
__device__ float g_K[(size_t)MDIM * DDIM];   // K in B-frag layout: hi|lo planes
__device__ float g_V[(size_t)MDIM * DDIM];   // fp32 V row-major
__device__ float g_att[(size_t)MDIM * DDIM];
__device__ float g_vmean[BDIM * HDIM * DKDIM];

// ---------------------------------------------------------------------------
__device__ __forceinline__ void mma_bf16_16x8x16(
    float* c, const uint32_t* a, uint32_t b0, uint32_t b1)
{
    asm volatile(
        "mma.sync.aligned.m16n8k16.row.col.f32.bf16.bf16.f32 "
        "{%0,%1,%2,%3}, {%4,%5,%6,%7}, {%8,%9}, {%0,%1,%2,%3};"
        : "+f"(c[0]), "+f"(c[1]), "+f"(c[2]), "+f"(c[3])
        : "r"(a[0]), "r"(a[1]), "r"(a[2]), "r"(a[3]), "r"(b0), "r"(b1));
}

__device__ __forceinline__ void split2(float x, float y, uint32_t& hi, uint32_t& lo)
{
    uint32_t bx = __float_as_uint(x), by = __float_as_uint(y);
    uint32_t hx = (bx + 0x7FFFu + ((bx >> 16) & 1u)) >> 16;
    uint32_t hy = (by + 0x7FFFu + ((by >> 16) & 1u)) >> 16;
    hi = hx | (hy << 16);
    float lx = x - __uint_as_float(hx << 16);
    float ly = y - __uint_as_float(hy << 16);
    uint32_t blx = __float_as_uint(lx), bly = __float_as_uint(ly);
    uint32_t hlx = (blx + 0x7FFFu + ((blx >> 16) & 1u)) >> 16;
    uint32_t hly = (bly + 0x7FFFu + ((bly >> 16) & 1u)) >> 16;
    lo = hlx | (hly << 16);
}

__device__ __forceinline__ float fexp(float x)
{
    float t = x * 1.4426950408889634f;
    t = fmaxf(t, -126.0f);
    float n = rintf(t);
    float f = t - n;
    float p = 0.0013333558f;
    p = fmaf(p, f, 0.0096181291f);
    p = fmaf(p, f, 0.0555041087f);
    p = fmaf(p, f, 0.2402265070f);
    p = fmaf(p, f, 0.6931471806f);
    p = fmaf(p, f, 1.0f);
    int e = (int)n;
    return __uint_as_float((uint32_t)((e + 127) << 23)) * p;
}

// ===========================================================================
// GEMM (TN) split-bf16. mode 0: fp32 out. mode 1: Q A-frag out. mode 2: K B-frag.
// ===========================================================================
__global__ void __launch_bounds__(256, 2) gemm_mma_kernel(
    const float* __restrict__ A, const float* __restrict__ W, void* __restrict__ Cv,
    int mode)
{
    __shared__ uint32_t Ahs[128][20];
    __shared__ uint32_t Als[128][20];
    __shared__ uint32_t Bhs[128][20];
    __shared__ uint32_t Bls[128][20];

    const int tid  = threadIdx.x;
    const int lane = tid & 31;
    const int w    = tid >> 5;
    const int wm   = (w & 3) * 32;
    const int wn   = (w >> 2) * 64;
    const int gid  = lane >> 2;
    const int tig  = lane & 3;
    const int bm   = blockIdx.y * 128;
    const int bn   = blockIdx.x * 128;

    const int r0   = tid >> 3;
    const int c0f  = (tid & 7) * 4;
    const int c0u  = (tid & 7) * 2;

    const float* Ap = A + (size_t)(bm + r0) * GK + c0f;
    const float* Wp = W + (size_t)(bn + r0) * GK + c0f;

    float acc[2][8][4];
#pragma unroll
    for (int mt = 0; mt < 2; mt++)
#pragma unroll
        for (int nt = 0; nt < 8; nt++)
#pragma unroll
            for (int q = 0; q < 4; q++) acc[mt][nt][q] = 0.f;

    for (int kc = 0; kc < GK / 32; kc++) {
        __syncthreads();
        const float* Ak = Ap + kc * 32;
        const float* Wk = Wp + kc * 32;
#pragma unroll
        for (int j = 0; j < 4; j++) {
            float4 a = *(const float4*)(Ak + (size_t)(32 * j) * GK);
            uint32_t h0, l0, h1, l1;
            split2(a.x, a.y, h0, l0); split2(a.z, a.w, h1, l1);
            *(uint2*)&Ahs[r0 + 32 * j][c0u] = make_uint2(h0, h1);
            *(uint2*)&Als[r0 + 32 * j][c0u] = make_uint2(l0, l1);
            float4 b = *(const float4*)(Wk + (size_t)(32 * j) * GK);
            split2(b.x, b.y, h0, l0); split2(b.z, b.w, h1, l1);
            *(uint2*)&Bhs[r0 + 32 * j][c0u] = make_uint2(h0, h1);
            *(uint2*)&Bls[r0 + 32 * j][c0u] = make_uint2(l0, l1);
        }
        __syncthreads();

#pragma unroll
        for (int ks = 0; ks < 2; ks++) {
            const int kb = ks * 8;
            uint32_t ah[2][4], al[2][4];
#pragma unroll
            for (int mt = 0; mt < 2; mt++) {
                const int rb = wm + mt * 16;
                ah[mt][0] = Ahs[rb + gid][kb + tig];
                ah[mt][1] = Ahs[rb + gid + 8][kb + tig];
                ah[mt][2] = Ahs[rb + gid][kb + tig + 4];
                ah[mt][3] = Ahs[rb + gid + 8][kb + tig + 4];
                al[mt][0] = Als[rb + gid][kb + tig];
                al[mt][1] = Als[rb + gid + 8][kb + tig];
                al[mt][2] = Als[rb + gid][kb + tig + 4];
                al[mt][3] = Als[rb + gid + 8][kb + tig + 4];
            }
#pragma unroll
            for (int nt = 0; nt < 8; nt++) {
                const int nb = wn + nt * 8 + gid;
                uint32_t bh0 = Bhs[nb][kb + tig], bh1 = Bhs[nb][kb + tig + 4];
                uint32_t bl0 = Bls[nb][kb + tig], bl1 = Bls[nb][kb + tig + 4];
                mma_bf16_16x8x16(acc[0][nt], ah[0], bh0, bh1);
                mma_bf16_16x8x16(acc[1][nt], ah[1], bh0, bh1);
                mma_bf16_16x8x16(acc[0][nt], ah[0], bl0, bl1);
                mma_bf16_16x8x16(acc[1][nt], ah[1], bl0, bl1);
                mma_bf16_16x8x16(acc[0][nt], al[0], bh0, bh1);
                mma_bf16_16x8x16(acc[1][nt], al[1], bh0, bh1);
            }
        }
    }

    if (mode == 0) {
        float* C = (float*)Cv;
#pragma unroll
        for (int mt = 0; mt < 2; mt++) {
            const int row = bm + wm + mt * 16 + gid;
#pragma unroll
            for (int nt = 0; nt < 8; nt++) {
                const int col = bn + wn + nt * 8 + tig * 2;
                *(float2*)(C + (size_t)row * GN + col) =
                    make_float2(acc[mt][nt][0], acc[mt][nt][1]);
                *(float2*)(C + (size_t)(row + 8) * GN + col) =
                    make_float2(acc[mt][nt][2], acc[mt][nt][3]);
            }
        }
    } else if (mode == 1) {
        // Q A-frag layout: uint4[((rb*16+h)*8+ks)*32+lane], hi|lo planes
        uint32_t* U = (uint32_t*)Cv;
        const int hh = bn >> 7;
#pragma unroll
        for (int mt = 0; mt < 2; mt++) {
            const int rb = (bm >> 4) + (w & 3) * 2 + mt;
#pragma unroll
            for (int j = 0; j < 4; j++) {
                const int ks = (w >> 2) * 4 + j;
                uint32_t h0, l0, h1, l1, h2, l2, h3, l3;
                split2(acc[mt][2 * j][0], acc[mt][2 * j][1], h0, l0);
                split2(acc[mt][2 * j][2], acc[mt][2 * j][3], h1, l1);
                split2(acc[mt][2 * j + 1][0], acc[mt][2 * j + 1][1], h2, l2);
                split2(acc[mt][2 * j + 1][2], acc[mt][2 * j + 1][3], h3, l3);
                size_t idx = ((((size_t)rb * 16 + hh) * 8 + ks) * 32 + lane) * 4;
                *(uint4*)(U + idx) = make_uint4(h0, h1, h2, h3);
                *(uint4*)(U + QLOFF + idx) = make_uint4(l0, l1, l2, l3);
            }
        }
    } else {
        // K B-frag layout: uint2[(((rb*16+h)*8+ks)*2+u)*32+lane], hi|lo planes
        uint32_t* U = (uint32_t*)Cv;
        const int hh = bn >> 7;
#pragma unroll
        for (int mt = 0; mt < 2; mt++) {
            const int rb = (bm >> 4) + (w & 3) * 2 + mt;
#pragma unroll
            for (int j = 0; j < 4; j++) {
                const int ks = (w >> 2) * 4 + j;
                uint32_t h0, l0, h1, l1, h2, l2, h3, l3;
                split2(acc[mt][2 * j][0], acc[mt][2 * j][1], h0, l0);
                split2(acc[mt][2 * j][2], acc[mt][2 * j][3], h1, l1);
                split2(acc[mt][2 * j + 1][0], acc[mt][2 * j + 1][1], h2, l2);
                split2(acc[mt][2 * j + 1][2], acc[mt][2 * j + 1][3], h3, l3);
                size_t idx = ((((size_t)rb * 16 + hh) * 8 + ks) * 2) * 64 + lane * 2;
                *(uint2*)(U + idx) = make_uint2(h0, h2);              // u=0
                *(uint2*)(U + KLOFF + idx) = make_uint2(l0, l2);
                *(uint2*)(U + idx + 64) = make_uint2(h1, h3);         // u=1
                *(uint2*)(U + KLOFF + idx + 64) = make_uint2(l1, l3);
            }
        }
    }
}

// ---------------------------------------------------------------------------
__global__ void vmean_kernel(const float* __restrict__ Vg, float* __restrict__ vmean)
{
    __shared__ float red[8][128];
    int bh = blockIdx.x;
    int b = bh >> 4, h = bh & 15;
    int d = threadIdx.x & 127;
    int ch = threadIdx.x >> 7;
    const float* Vb = Vg + ((size_t)b * SDIM + ch * 256) * DDIM + h * DKDIM + d;
    float s = 0.f;
    for (int j = 0; j < 256; j++) s += Vb[(size_t)j * DDIM];
    red[ch][d] = s;
    __syncthreads();
    if (ch == 0) {
        float t = red[0][d] + red[1][d] + red[2][d] + red[3][d]
                + red[4][d] + red[5][d] + red[6][d] + red[7][d];
        vmean[bh * DKDIM + d] = t * (1.f / (float)SDIM);
    }
}

// ===========================================================================
// Flash attention, q-tile 64, 8 warps = 4 q-blocks x 2 halves.
// QK: warp (qb,dh) = 16q x 32keys (keys dh*32..+31). PV: 16q x 64d (d half dh).
// P exchanged via frag-layout smem overlaid on retired K-hi region.
// SMEM u32: QH[0,4096) QL[4096,8192) | KH[8192,12288) KL[12288,16384)
//           (P: hi [8192,10240) lo [10240,12288))
//           VH[16384,20736) VL[20736,25088) | pmx[25088] pls[25216] mask[25344]
// ===========================================================================
#define AQ 0
#define AQL 4096
#define AK 8192
#define AKL 12288
#define AP 8192
#define APL 10240
#define AV 16384
#define AVL 20736
#define APMX 25088
#define APLS 25216
#define AMSK 25344
#define ATT_U32 25408
#define ATT_SMEM_BYTES (ATT_U32 * 4)   // 101632

__global__ void __launch_bounds__(256, 2) attn_mma_kernel(
    const uint32_t* __restrict__ Qp, const uint32_t* __restrict__ Kp,
    const float* __restrict__ Vg, const int* __restrict__ maskg,
    const float* __restrict__ vmean, float* __restrict__ Og)
{
    extern __shared__ uint32_t smu[];
    float* pmxF = (float*)(smu + APMX);
    float* plsF = (float*)(smu + APLS);
    int* maskS  = (int*)(smu + AMSK);

    const int qt = blockIdx.x, h = blockIdx.y, b = blockIdx.z;
    const int tid = threadIdx.x, lane = tid & 31, w = tid >> 5;
    const int gid = lane >> 2, tig = lane & 3;
    const int qb = w & 3, dh = w >> 2;
    const int q0 = qt * 64;
    const int r1 = qb * 16 + gid, r2 = r1 + 8;

    const uint4* Qf4 = (const uint4*)Qp;
    const uint4* Kf4 = (const uint4*)Kp;
    const float* Vbase = Vg + (size_t)(b * SDIM) * DDIM + h * DKDIM;
    const int* mb = maskg + b * SDIM;

    // Stage Q fragments (once): 4 blocks x 256 uint4 per plane
    for (int i = tid; i < 1024; i += 256) {
        int qbl = i >> 8, j = i & 255;
        size_t src = ((size_t)(b * 128 + qt * 4 + qbl) * 16 + h) * 256 + j;
        ((uint4*)smu)[i] = Qf4[src];
        ((uint4*)smu)[1024 + i] = Qf4[QLOFF4 + src];
    }

    float m1 = -3.402823466e38f, m2 = -3.402823466e38f;
    float l1 = 0.f, l2 = 0.f;
    float o[8][4];
#pragma unroll
    for (int nt = 0; nt < 8; nt++)
#pragma unroll
        for (int q = 0; q < 4; q++) o[nt][q] = 0.f;

    const int nkt = qt + 1;
    for (int kt = 0; kt < nkt; kt++) {
        const int k0 = kt * 64;
        __syncthreads();  // prev PV reads (and Q stores, iter 0) complete

        // K fragments: 4 blocks x 256 uint4 per plane
        for (int i = tid; i < 1024; i += 256) {
            int rbl = i >> 8, j = i & 255;
            size_t src = ((size_t)(b * 128 + kt * 4 + rbl) * 16 + h) * 256 + j;
            ((uint4*)smu)[(AK >> 2) + i] = Kf4[src];
            ((uint4*)smu)[(AKL >> 2) + i] = Kf4[KLOFF4 + src];
        }
        // V: fp32 -> key-paired split, [32 kp][136]
        for (int i = tid; i < 1024; i += 256) {
            int kp = i >> 5, d4 = (i & 31) * 4;
            float4 va = *(const float4*)(Vbase + (size_t)(k0 + 2 * kp) * DDIM + d4);
            float4 vb = *(const float4*)(Vbase + (size_t)(k0 + 2 * kp + 1) * DDIM + d4);
            uint32_t h0, l0, h1, l1u, h2, l2u, h3, l3;
            split2(va.x, vb.x, h0, l0); split2(va.y, vb.y, h1, l1u);
            split2(va.z, vb.z, h2, l2u); split2(va.w, vb.w, h3, l3);
            *(uint4*)&smu[AV + kp * 136 + d4] = make_uint4(h0, h1, h2, h3);
            *(uint4*)&smu[AVL + kp * 136 + d4] = make_uint4(l0, l1u, l2u, l3);
        }
        if (tid < 64) maskS[tid] = mb[k0 + tid];
        __syncthreads();

        // QK: warp keys dh*32 + nt*8 (nt 0..3)
        float sc[4][4];
#pragma unroll
        for (int nt = 0; nt < 4; nt++)
#pragma unroll
            for (int q = 0; q < 4; q++) sc[nt][q] = 0.f;

#pragma unroll
        for (int ks = 0; ks < 8; ks++) {
            uint4 ahv = *(const uint4*)&smu[AQ + ((qb * 8 + ks) * 32 + lane) * 4];
            uint4 alv = *(const uint4*)&smu[AQL + ((qb * 8 + ks) * 32 + lane) * 4];
            uint32_t ah[4] = {ahv.x, ahv.y, ahv.z, ahv.w};
            uint32_t al[4] = {alv.x, alv.y, alv.z, alv.w};
#pragma unroll
            for (int nt = 0; nt < 4; nt++) {
                const int ntg = dh * 4 + nt;
                const int base = (((ntg >> 1) * 8 + ks) * 2 + (ntg & 1)) * 64 + lane * 2;
                uint2 kh = *(const uint2*)&smu[AK + base];
                uint2 kl = *(const uint2*)&smu[AKL + base];
                mma_bf16_16x8x16(sc[nt], ah, kh.x, kh.y);
                mma_bf16_16x8x16(sc[nt], ah, kl.x, kl.y);
                mma_bf16_16x8x16(sc[nt], al, kh.x, kh.y);
            }
        }

        // Mask + scale + per-half tile max
        float tm1 = -3.402823466e38f, tm2 = -3.402823466e38f;
#pragma unroll
        for (int nt = 0; nt < 4; nt++) {
#pragma unroll
            for (int jj = 0; jj < 2; jj++) {
                const int col = dh * 32 + nt * 8 + tig * 2 + jj;
                const int jg = k0 + col;
                const bool ok = (maskS[col] != 0);
                float s0 = (ok && jg <= q0 + r1) ? sc[nt][jj] * SCALE : NEGV;
                float s1 = (ok && jg <= q0 + r2) ? sc[nt][2 + jj] * SCALE : NEGV;
                sc[nt][jj] = s0; sc[nt][2 + jj] = s1;
                tm1 = fmaxf(tm1, s0); tm2 = fmaxf(tm2, s1);
            }
        }
        tm1 = fmaxf(tm1, __shfl_xor_sync(0xffffffffu, tm1, 1));
        tm1 = fmaxf(tm1, __shfl_xor_sync(0xffffffffu, tm1, 2));
        tm2 = fmaxf(tm2, __shfl_xor_sync(0xffffffffu, tm2, 1));
        tm2 = fmaxf(tm2, __shfl_xor_sync(0xffffffffu, tm2, 2));
        if (tig == 0) { pmxF[dh * 64 + r1] = tm1; pmxF[dh * 64 + r2] = tm2; }
        __syncthreads();  // pmx ready; ALL K reads done -> K-hi reusable for P

        const float mn1 = fmaxf(m1, fmaxf(pmxF[r1], pmxF[64 + r1]));
        const float mn2 = fmaxf(m2, fmaxf(pmxF[r2], pmxF[64 + r2]));
        const float c1 = fexp(m1 - mn1), c2 = fexp(m2 - mn2);
        m1 = mn1; m2 = mn2;

        float s1sum = 0.f, s2sum = 0.f;
#pragma unroll
        for (int nt = 0; nt < 4; nt++) {
            sc[nt][0] = fexp(sc[nt][0] - mn1);
            sc[nt][1] = fexp(sc[nt][1] - mn1);
            sc[nt][2] = fexp(sc[nt][2] - mn2);
            sc[nt][3] = fexp(sc[nt][3] - mn2);
            s1sum += sc[nt][0] + sc[nt][1];
            s2sum += sc[nt][2] + sc[nt][3];
        }
        s1sum += __shfl_xor_sync(0xffffffffu, s1sum, 1);
        s1sum += __shfl_xor_sync(0xffffffffu, s1sum, 2);
        s2sum += __shfl_xor_sync(0xffffffffu, s2sum, 1);
        s2sum += __shfl_xor_sync(0xffffffffu, s2sum, 2);
        if (tig == 0) { plsF[dh * 64 + r1] = s1sum; plsF[dh * 64 + r2] = s2sum; }

        // Write P A-frags (ks2 = dh*2 + s) into retired K region
#pragma unroll
        for (int s = 0; s < 2; s++) {
            const int ks2 = dh * 2 + s;
            uint32_t h0, l0, h1, l1u, h2, l2u, h3, l3;
            split2(sc[2 * s][0], sc[2 * s][1], h0, l0);
            split2(sc[2 * s][2], sc[2 * s][3], h1, l1u);
            split2(sc[2 * s + 1][0], sc[2 * s + 1][1], h2, l2u);
            split2(sc[2 * s + 1][2], sc[2 * s + 1][3], h3, l3);
            const int idx = ((qb * 4 + ks2) * 32 + lane) * 4;
            *(uint4*)&smu[AP + idx] = make_uint4(h0, h1, h2, h3);
            *(uint4*)&smu[APL + idx] = make_uint4(l0, l1u, l2u, l3);
        }
        __syncthreads();  // P + pls visible

        l1 = l1 * c1 + plsF[r1] + plsF[64 + r1];
        l2 = l2 * c2 + plsF[r2] + plsF[64 + r2];

#pragma unroll
        for (int nt = 0; nt < 8; nt++) {
            o[nt][0] *= c1; o[nt][1] *= c1; o[nt][2] *= c2; o[nt][3] *= c2;
        }

        // PV: A = P frags (all 4 ks2), B = V (d half dh)
#pragma unroll
        for (int ks2 = 0; ks2 < 4; ks2++) {
            const int idx = ((qb * 4 + ks2) * 32 + lane) * 4;
            uint4 phv = *(const uint4*)&smu[AP + idx];
            uint4 plv = *(const uint4*)&smu[APL + idx];
            uint32_t ph[4] = {phv.x, phv.y, phv.z, phv.w};
            uint32_t pl[4] = {plv.x, plv.y, plv.z, plv.w};
#pragma unroll
            for (int nt = 0; nt < 8; nt++) {
                const int d = dh * 64 + nt * 8 + gid;
                uint32_t vh0 = smu[AV + (ks2 * 8 + tig) * 136 + d];
                uint32_t vh1 = smu[AV + (ks2 * 8 + 4 + tig) * 136 + d];
                uint32_t vl0 = smu[AVL + (ks2 * 8 + tig) * 136 + d];
                uint32_t vl1 = smu[AVL + (ks2 * 8 + 4 + tig) * 136 + d];
                mma_bf16_16x8x16(o[nt], ph, vh0, vh1);
                mma_bf16_16x8x16(o[nt], ph, vl0, vl1);
                mma_bf16_16x8x16(o[nt], pl, vh0, vh1);
            }
        }
    }

    // Epilogue
    const float inv1 = 1.f / l1, inv2 = 1.f / l2;
    const bool dead1 = m1 < -1e8f, dead2 = m2 < -1e8f;
    const float* vm = vmean + ((size_t)b * HDIM + h) * DKDIM;
    float* O1 = Og + ((size_t)b * SDIM + q0 + r1) * DDIM + h * DKDIM;
    float* O2 = Og + ((size_t)b * SDIM + q0 + r2) * DDIM + h * DKDIM;
#pragma unroll
    for (int nt = 0; nt < 8; nt++) {
        const int d = dh * 64 + nt * 8 + tig * 2;
        float2 u1 = dead1 ? make_float2(vm[d], vm[d + 1])
                          : make_float2(o[nt][0] * inv1, o[nt][1] * inv1);
        float2 u2 = dead2 ? make_float2(vm[d], vm[d + 1])
                          : make_float2(o[nt][2] * inv2, o[nt][3] * inv2);
        *(float2*)(O1 + d) = u1;
        *(float2*)(O2 + d) = u2;
    }
}

// ---------------------------------------------------------------------------
extern "C" void kernel_launch(void* const* d_in, const int* in_sizes, int n_in,
                              void* d_out, int out_size)
{
    const float* x    = (const float*)d_in[0];
    const int*   mask = (const int*)d_in[1];
    const float* wq   = (const float*)d_in[2];
    const float* wk   = (const float*)d_in[3];
    const float* wv   = (const float*)d_in[4];
    const float* wo   = (const float*)d_in[5];
    float* out = (float*)d_out;

    float *pQ, *pK, *pV, *pAtt, *pVm;
    cudaGetSymbolAddress((void**)&pQ, g_Q);
    cudaGetSymbolAddress((void**)&pK, g_K);
    cudaGetSymbolAddress((void**)&pV, g_V);
    cudaGetSymbolAddress((void**)&pAtt, g_att);
    cudaGetSymbolAddress((void**)&pVm, g_vmean);

    cudaFuncSetAttribute(attn_mma_kernel, cudaFuncAttributeMaxDynamicSharedMemorySize,
                         ATT_SMEM_BYTES);

    dim3 gg(GN / 128, MDIM / 128);  // (16, 64)
    gemm_mma_kernel<<<gg, 256>>>(x, wq, pQ, 1);   // Q -> A-frag layout
    gemm_mma_kernel<<<gg, 256>>>(x, wk, pK, 2);   // K -> B-frag layout
    gemm_mma_kernel<<<gg, 256>>>(x, wv, pV, 0);   // V fp32

    vmean_kernel<<<BDIM * HDIM, 1024>>>(pV, pVm);

    attn_mma_kernel<<<dim3(SDIM / 64, HDIM, BDIM), 256, ATT_SMEM_BYTES>>>(
        (const uint32_t*)pQ, (const uint32_t*)pK, pV, mask, pVm, pAtt);

    gemm_mma_kernel<<<gg, 256>>>(pAtt, wo, out, 0);
}

// round 9
// speedup vs baseline: 1.2191x; 1.0573x over previous
#include <cuda_runtime.h>
#include <cstdint>
#include <math.h>

// Problem constants
#define BDIM 4
#define SDIM 2048
#define DDIM 2048
#define HDIM 16
#define DKDIM 128
#define MDIM (BDIM * SDIM)   // 8192
#define GK 2048
#define GN 2048

#define NEGV (-1e9f)
#define SCALE 0.08838834764831845f  // 1/sqrt(128)

// Fragment-plane offsets
#define QLOFF 8388608ull       // u32 offset of lo plane (Q A-frag layout)
#define KLOFF 8388608ull       // u32 offset of lo plane (K B-frag layout)
#define QLOFF4 2097152ull      // same in uint4 units
#define KLOFF4 2097152ull
#define VLOFF4 2097152ull      // V-frag lo plane in uint4 units
#define VLOFF2 4194304u        // V-frag lo plane in uint2 units

// Scratch (device globals — no cudaMalloc allowed)
__device__ float g_Q[(size_t)MDIM * DDIM];     // Q in A-frag layout: hi|lo planes
__device__ float g_K[(size_t)MDIM * DDIM];     // K in B-frag layout: hi|lo planes
__device__ float g_V[(size_t)MDIM * DDIM];     // fp32 V row-major
__device__ uint32_t g_VF[16777216];            // V in PV B-frag layout: hi|lo planes
__device__ float g_att[(size_t)MDIM * DDIM];
__device__ float g_vmean[BDIM * HDIM * DKDIM];

// ---------------------------------------------------------------------------
__device__ __forceinline__ void mma_bf16_16x8x16(
    float* c, const uint32_t* a, uint32_t b0, uint32_t b1)
{
    asm volatile(
        "mma.sync.aligned.m16n8k16.row.col.f32.bf16.bf16.f32 "
        "{%0,%1,%2,%3}, {%4,%5,%6,%7}, {%8,%9}, {%0,%1,%2,%3};"
        : "+f"(c[0]), "+f"(c[1]), "+f"(c[2]), "+f"(c[3])
        : "r"(a[0]), "r"(a[1]), "r"(a[2]), "r"(a[3]), "r"(b0), "r"(b1));
}

__device__ __forceinline__ void split2(float x, float y, uint32_t& hi, uint32_t& lo)
{
    uint32_t bx = __float_as_uint(x), by = __float_as_uint(y);
    uint32_t hx = (bx + 0x7FFFu + ((bx >> 16) & 1u)) >> 16;
    uint32_t hy = (by + 0x7FFFu + ((by >> 16) & 1u)) >> 16;
    hi = hx | (hy << 16);
    float lx = x - __uint_as_float(hx << 16);
    float ly = y - __uint_as_float(hy << 16);
    uint32_t blx = __float_as_uint(lx), bly = __float_as_uint(ly);
    uint32_t hlx = (blx + 0x7FFFu + ((blx >> 16) & 1u)) >> 16;
    uint32_t hly = (bly + 0x7FFFu + ((bly >> 16) & 1u)) >> 16;
    lo = hlx | (hly << 16);
}

__device__ __forceinline__ float fexp(float x)
{
    float t = x * 1.4426950408889634f;
    t = fmaxf(t, -126.0f);
    float n = rintf(t);
    float f = t - n;
    float p = 0.0013333558f;
    p = fmaf(p, f, 0.0096181291f);
    p = fmaf(p, f, 0.0555041087f);
    p = fmaf(p, f, 0.2402265070f);
    p = fmaf(p, f, 0.6931471806f);
    p = fmaf(p, f, 1.0f);
    int e = (int)n;
    return __uint_as_float((uint32_t)((e + 127) << 23)) * p;
}

__device__ __forceinline__ uint32_t smem_u32(const void* p) {
    uint32_t a;
    asm("{ .reg .u64 t; cvta.to.shared.u64 t, %1; cvt.u32.u64 %0, t; }" : "=r"(a) : "l"(p));
    return a;
}

__device__ __forceinline__ void cp16(uint32_t dst, const void* src) {
    asm volatile("cp.async.ca.shared.global [%0], [%1], 16;" :: "r"(dst), "l"(src));
}
#define CPCOMMIT() asm volatile("cp.async.commit_group;" ::: "memory")
#define CPWAIT0()  asm volatile("cp.async.wait_group 0;" ::: "memory")

// ===========================================================================
// GEMM (TN) split-bf16. mode 0: fp32 out. mode 1: Q A-frag out. mode 2: K B-frag.
// ===========================================================================
__global__ void __launch_bounds__(256, 2) gemm_mma_kernel(
    const float* __restrict__ A, const float* __restrict__ W, void* __restrict__ Cv,
    int mode)
{
    __shared__ uint32_t Ahs[128][20];
    __shared__ uint32_t Als[128][20];
    __shared__ uint32_t Bhs[128][20];
    __shared__ uint32_t Bls[128][20];

    const int tid  = threadIdx.x;
    const int lane = tid & 31;
    const int w    = tid >> 5;
    const int wm   = (w & 3) * 32;
    const int wn   = (w >> 2) * 64;
    const int gid  = lane >> 2;
    const int tig  = lane & 3;
    const int bm   = blockIdx.y * 128;
    const int bn   = blockIdx.x * 128;

    const int r0   = tid >> 3;
    const int c0f  = (tid & 7) * 4;
    const int c0u  = (tid & 7) * 2;

    const float* Ap = A + (size_t)(bm + r0) * GK + c0f;
    const float* Wp = W + (size_t)(bn + r0) * GK + c0f;

    float acc[2][8][4];
#pragma unroll
    for (int mt = 0; mt < 2; mt++)
#pragma unroll
        for (int nt = 0; nt < 8; nt++)
#pragma unroll
            for (int q = 0; q < 4; q++) acc[mt][nt][q] = 0.f;

    for (int kc = 0; kc < GK / 32; kc++) {
        __syncthreads();
        const float* Ak = Ap + kc * 32;
        const float* Wk = Wp + kc * 32;
#pragma unroll
        for (int j = 0; j < 4; j++) {
            float4 a = *(const float4*)(Ak + (size_t)(32 * j) * GK);
            uint32_t h0, l0, h1, l1;
            split2(a.x, a.y, h0, l0); split2(a.z, a.w, h1, l1);
            *(uint2*)&Ahs[r0 + 32 * j][c0u] = make_uint2(h0, h1);
            *(uint2*)&Als[r0 + 32 * j][c0u] = make_uint2(l0, l1);
            float4 b = *(const float4*)(Wk + (size_t)(32 * j) * GK);
            split2(b.x, b.y, h0, l0); split2(b.z, b.w, h1, l1);
            *(uint2*)&Bhs[r0 + 32 * j][c0u] = make_uint2(h0, h1);
            *(uint2*)&Bls[r0 + 32 * j][c0u] = make_uint2(l0, l1);
        }
        __syncthreads();

#pragma unroll
        for (int ks = 0; ks < 2; ks++) {
            const int kb = ks * 8;
            uint32_t ah[2][4], al[2][4];
#pragma unroll
            for (int mt = 0; mt < 2; mt++) {
                const int rb = wm + mt * 16;
                ah[mt][0] = Ahs[rb + gid][kb + tig];
                ah[mt][1] = Ahs[rb + gid + 8][kb + tig];
                ah[mt][2] = Ahs[rb + gid][kb + tig + 4];
                ah[mt][3] = Ahs[rb + gid + 8][kb + tig + 4];
                al[mt][0] = Als[rb + gid][kb + tig];
                al[mt][1] = Als[rb + gid + 8][kb + tig];
                al[mt][2] = Als[rb + gid][kb + tig + 4];
                al[mt][3] = Als[rb + gid + 8][kb + tig + 4];
            }
#pragma unroll
            for (int nt = 0; nt < 8; nt++) {
                const int nb = wn + nt * 8 + gid;
                uint32_t bh0 = Bhs[nb][kb + tig], bh1 = Bhs[nb][kb + tig + 4];
                uint32_t bl0 = Bls[nb][kb + tig], bl1 = Bls[nb][kb + tig + 4];
                mma_bf16_16x8x16(acc[0][nt], ah[0], bh0, bh1);
                mma_bf16_16x8x16(acc[1][nt], ah[1], bh0, bh1);
                mma_bf16_16x8x16(acc[0][nt], ah[0], bl0, bl1);
                mma_bf16_16x8x16(acc[1][nt], ah[1], bl0, bl1);
                mma_bf16_16x8x16(acc[0][nt], al[0], bh0, bh1);
                mma_bf16_16x8x16(acc[1][nt], al[1], bh0, bh1);
            }
        }
    }

    if (mode == 0) {
        float* C = (float*)Cv;
#pragma unroll
        for (int mt = 0; mt < 2; mt++) {
            const int row = bm + wm + mt * 16 + gid;
#pragma unroll
            for (int nt = 0; nt < 8; nt++) {
                const int col = bn + wn + nt * 8 + tig * 2;
                *(float2*)(C + (size_t)row * GN + col) =
                    make_float2(acc[mt][nt][0], acc[mt][nt][1]);
                *(float2*)(C + (size_t)(row + 8) * GN + col) =
                    make_float2(acc[mt][nt][2], acc[mt][nt][3]);
            }
        }
    } else if (mode == 1) {
        uint32_t* U = (uint32_t*)Cv;
        const int hh = bn >> 7;
#pragma unroll
        for (int mt = 0; mt < 2; mt++) {
            const int rb = (bm >> 4) + (w & 3) * 2 + mt;
#pragma unroll
            for (int j = 0; j < 4; j++) {
                const int ks = (w >> 2) * 4 + j;
                uint32_t h0, l0, h1, l1, h2, l2, h3, l3;
                split2(acc[mt][2 * j][0], acc[mt][2 * j][1], h0, l0);
                split2(acc[mt][2 * j][2], acc[mt][2 * j][3], h1, l1);
                split2(acc[mt][2 * j + 1][0], acc[mt][2 * j + 1][1], h2, l2);
                split2(acc[mt][2 * j + 1][2], acc[mt][2 * j + 1][3], h3, l3);
                size_t idx = ((((size_t)rb * 16 + hh) * 8 + ks) * 32 + lane) * 4;
                *(uint4*)(U + idx) = make_uint4(h0, h1, h2, h3);
                *(uint4*)(U + QLOFF + idx) = make_uint4(l0, l1, l2, l3);
            }
        }
    } else {
        uint32_t* U = (uint32_t*)Cv;
        const int hh = bn >> 7;
#pragma unroll
        for (int mt = 0; mt < 2; mt++) {
            const int rb = (bm >> 4) + (w & 3) * 2 + mt;
#pragma unroll
            for (int j = 0; j < 4; j++) {
                const int ks = (w >> 2) * 4 + j;
                uint32_t h0, l0, h1, l1, h2, l2, h3, l3;
                split2(acc[mt][2 * j][0], acc[mt][2 * j][1], h0, l0);
                split2(acc[mt][2 * j][2], acc[mt][2 * j][3], h1, l1);
                split2(acc[mt][2 * j + 1][0], acc[mt][2 * j + 1][1], h2, l2);
                split2(acc[mt][2 * j + 1][2], acc[mt][2 * j + 1][3], h3, l3);
                size_t idx = ((((size_t)rb * 16 + hh) * 8 + ks) * 2) * 64 + lane * 2;
                *(uint2*)(U + idx) = make_uint2(h0, h2);
                *(uint2*)(U + KLOFF + idx) = make_uint2(l0, l2);
                *(uint2*)(U + idx + 64) = make_uint2(h1, h3);
                *(uint2*)(U + KLOFF + idx + 64) = make_uint2(l1, l3);
            }
        }
    }
}

// ---------------------------------------------------------------------------
__global__ void vmean_kernel(const float* __restrict__ Vg, float* __restrict__ vmean)
{
    __shared__ float red[8][128];
    int bh = blockIdx.x;
    int b = bh >> 4, h = bh & 15;
    int d = threadIdx.x & 127;
    int ch = threadIdx.x >> 7;
    const float* Vb = Vg + ((size_t)b * SDIM + ch * 256) * DDIM + h * DKDIM + d;
    float s = 0.f;
    for (int j = 0; j < 256; j++) s += Vb[(size_t)j * DDIM];
    red[ch][d] = s;
    __syncthreads();
    if (ch == 0) {
        float t = red[0][d] + red[1][d] + red[2][d] + red[3][d]
                + red[4][d] + red[5][d] + red[6][d] + red[7][d];
        vmean[bh * DKDIM + d] = t * (1.f / (float)SDIM);
    }
}

// ---------------------------------------------------------------------------
// V pre-split into PV B-fragment layout.
// Per (b,kb,h): 16 keys x 128 d -> 16 nb x 32 lanes uint2 (b0,b1), hi|lo planes.
// ---------------------------------------------------------------------------
__global__ void vsplit_kernel(const float* __restrict__ Vg, uint32_t* __restrict__ VF)
{
    __shared__ float vs[16][132];
    const int h = blockIdx.x, kb = blockIdx.y, b = blockIdx.z;
    const int tid = threadIdx.x;  // 128

    const float* src = Vg + ((size_t)(b * SDIM + kb * 16)) * DDIM + h * DKDIM;
#pragma unroll
    for (int j = 0; j < 4; j++) {
        int idx = tid + j * 128;
        int r = idx >> 5, c4 = (idx & 31) * 4;
        *(float4*)&vs[r][c4] = *(const float4*)(src + (size_t)r * DDIM + c4);
    }
    __syncthreads();

    uint2* VF2 = (uint2*)VF;
    const uint32_t base = ((uint32_t)((b * 128 + kb) * 16 + h)) * 512;
#pragma unroll
    for (int j = 0; j < 4; j++) {
        int i = tid + j * 128;        // 0..511
        int nb = i >> 5, lane = i & 31, gid = lane >> 2, tig = lane & 3;
        int d = nb * 8 + gid;
        uint32_t b0h, b0l, b1h, b1l;
        split2(vs[2 * tig][d],     vs[2 * tig + 1][d], b0h, b0l);
        split2(vs[2 * tig + 8][d], vs[2 * tig + 9][d], b1h, b1l);
        VF2[base + i] = make_uint2(b0h, b1h);
        VF2[VLOFF2 + base + i] = make_uint2(b0l, b1l);
    }
}

// ===========================================================================
// Flash attention, q-tile 64, 8 warps = 4 q-blocks x 2 halves, 2 CTAs/SM.
// All operands pre-split into mma fragment layouts; staging via cp.async.
// SMEM u32: Q[0,8192) K[8192,16384) (P overlays [8192,12288))
//           V[16384,24576) | pmx[24576] pls[24704] mask[24832]
// ===========================================================================
#define AQ 0
#define AQL 4096
#define AK 8192
#define AKL 12288
#define AP 8192
#define APL 10240
#define AV 16384
#define AVL 20480
#define APMX 24576
#define APLS 24704
#define AMSK 24832
#define ATT_U32 24896
#define ATT_SMEM_BYTES (ATT_U32 * 4)   // 99584

__global__ void __launch_bounds__(256, 2) attn_mma_kernel(
    const uint4* __restrict__ Qf4, const uint4* __restrict__ Kf4,
    const uint4* __restrict__ VF4, const int* __restrict__ maskg,
    const float* __restrict__ vmean, float* __restrict__ Og)
{
    extern __shared__ uint32_t smu[];
    float* pmxF = (float*)(smu + APMX);
    float* plsF = (float*)(smu + APLS);
    int* maskS  = (int*)(smu + AMSK);
    const uint32_t sb = smem_u32(smu);

    const int qt = (int)gridDim.x - 1 - (int)blockIdx.x;  // longest first
    const int h = blockIdx.y, b = blockIdx.z;
    const int tid = threadIdx.x, lane = tid & 31, w = tid >> 5;
    const int gid = lane >> 2, tig = lane & 3;
    const int qb = w & 3, dh = w >> 2;
    const int q0 = qt * 64;
    const int r1 = qb * 16 + gid, r2 = r1 + 8;

    const int* mb = maskg + b * SDIM;

    // Stage Q fragments via cp.async (waited at first iteration's CPWAIT0)
    for (int i = tid; i < 1024; i += 256) {
        int qbl = i >> 8, j = i & 255;
        size_t src = ((size_t)(b * 128 + qt * 4 + qbl) * 16 + h) * 256 + j;
        cp16(sb + AQ * 4 + i * 16, Qf4 + src);
        cp16(sb + AQL * 4 + i * 16, Qf4 + QLOFF4 + src);
    }
    CPCOMMIT();

    float m1 = -3.402823466e38f, m2 = -3.402823466e38f;
    float l1 = 0.f, l2 = 0.f;
    float o[8][4];
#pragma unroll
    for (int nt = 0; nt < 8; nt++)
#pragma unroll
        for (int q = 0; q < 4; q++) o[nt][q] = 0.f;

    const int nkt = qt + 1;
    for (int kt = 0; kt < nkt; kt++) {
        const int k0 = kt * 64;
        __syncthreads();  // prev PV reads complete -> K/P region reusable

        // K + V fragments via cp.async (pure copies, pre-split)
        for (int i = tid; i < 1024; i += 256) {
            int rbl = i >> 8, j = i & 255;
            size_t srcK = ((size_t)(b * 128 + kt * 4 + rbl) * 16 + h) * 256 + j;
            cp16(sb + AK * 4 + i * 16, Kf4 + srcK);
            cp16(sb + AKL * 4 + i * 16, Kf4 + KLOFF4 + srcK);
            cp16(sb + AV * 4 + i * 16, VF4 + srcK);
            cp16(sb + AVL * 4 + i * 16, VF4 + VLOFF4 + srcK);
        }
        if (tid < 64) maskS[tid] = mb[k0 + tid];
        CPCOMMIT();
        CPWAIT0();
        __syncthreads();

        // QK: dual accumulation chains (ks 0-3 -> sc, ks 4-7 -> scB)
        float sc[4][4], scB[4][4];
#pragma unroll
        for (int nt = 0; nt < 4; nt++)
#pragma unroll
            for (int q = 0; q < 4; q++) { sc[nt][q] = 0.f; scB[nt][q] = 0.f; }

#pragma unroll
        for (int ks = 0; ks < 8; ks++) {
            uint4 ahv = *(const uint4*)&smu[AQ + ((qb * 8 + ks) * 32 + lane) * 4];
            uint4 alv = *(const uint4*)&smu[AQL + ((qb * 8 + ks) * 32 + lane) * 4];
            uint32_t ah[4] = {ahv.x, ahv.y, ahv.z, ahv.w};
            uint32_t al[4] = {alv.x, alv.y, alv.z, alv.w};
            float (*acc)[4] = (ks < 4) ? sc : scB;
#pragma unroll
            for (int nt = 0; nt < 4; nt++) {
                const int ntg = dh * 4 + nt;
                const int base = (((ntg >> 1) * 8 + ks) * 2 + (ntg & 1)) * 64 + lane * 2;
                uint2 kh = *(const uint2*)&smu[AK + base];
                uint2 kl = *(const uint2*)&smu[AKL + base];
                mma_bf16_16x8x16(acc[nt], ah, kh.x, kh.y);
                mma_bf16_16x8x16(acc[nt], ah, kl.x, kl.y);
                mma_bf16_16x8x16(acc[nt], al, kh.x, kh.y);
            }
        }
#pragma unroll
        for (int nt = 0; nt < 4; nt++)
#pragma unroll
            for (int q = 0; q < 4; q++) sc[nt][q] += scB[nt][q];

        // Mask + scale + per-half tile max
        float tm1 = -3.402823466e38f, tm2 = -3.402823466e38f;
#pragma unroll
        for (int nt = 0; nt < 4; nt++) {
#pragma unroll
            for (int jj = 0; jj < 2; jj++) {
                const int col = dh * 32 + nt * 8 + tig * 2 + jj;
                const int jg = k0 + col;
                const bool ok = (maskS[col] != 0);
                float s0 = (ok && jg <= q0 + r1) ? sc[nt][jj] * SCALE : NEGV;
                float s1 = (ok && jg <= q0 + r2) ? sc[nt][2 + jj] * SCALE : NEGV;
                sc[nt][jj] = s0; sc[nt][2 + jj] = s1;
                tm1 = fmaxf(tm1, s0); tm2 = fmaxf(tm2, s1);
            }
        }
        tm1 = fmaxf(tm1, __shfl_xor_sync(0xffffffffu, tm1, 1));
        tm1 = fmaxf(tm1, __shfl_xor_sync(0xffffffffu, tm1, 2));
        tm2 = fmaxf(tm2, __shfl_xor_sync(0xffffffffu, tm2, 1));
        tm2 = fmaxf(tm2, __shfl_xor_sync(0xffffffffu, tm2, 2));
        if (tig == 0) { pmxF[dh * 64 + r1] = tm1; pmxF[dh * 64 + r2] = tm2; }
        __syncthreads();  // pmx ready; K reads done -> K-hi reusable for P

        const float mn1 = fmaxf(m1, fmaxf(pmxF[r1], pmxF[64 + r1]));
        const float mn2 = fmaxf(m2, fmaxf(pmxF[r2], pmxF[64 + r2]));
        const float c1 = fexp(m1 - mn1), c2 = fexp(m2 - mn2);
        m1 = mn1; m2 = mn2;

        float s1sum = 0.f, s2sum = 0.f;
#pragma unroll
        for (int nt = 0; nt < 4; nt++) {
            sc[nt][0] = fexp(sc[nt][0] - mn1);
            sc[nt][1] = fexp(sc[nt][1] - mn1);
            sc[nt][2] = fexp(sc[nt][2] - mn2);
            sc[nt][3] = fexp(sc[nt][3] - mn2);
            s1sum += sc[nt][0] + sc[nt][1];
            s2sum += sc[nt][2] + sc[nt][3];
        }
        s1sum += __shfl_xor_sync(0xffffffffu, s1sum, 1);
        s1sum += __shfl_xor_sync(0xffffffffu, s1sum, 2);
        s2sum += __shfl_xor_sync(0xffffffffu, s2sum, 1);
        s2sum += __shfl_xor_sync(0xffffffffu, s2sum, 2);
        if (tig == 0) { plsF[dh * 64 + r1] = s1sum; plsF[dh * 64 + r2] = s2sum; }

        // Write P A-frags into retired K region
#pragma unroll
        for (int s = 0; s < 2; s++) {
            const int ks2 = dh * 2 + s;
            uint32_t h0, l0, h1, l1u, h2, l2u, h3, l3;
            split2(sc[2 * s][0], sc[2 * s][1], h0, l0);
            split2(sc[2 * s][2], sc[2 * s][3], h1, l1u);
            split2(sc[2 * s + 1][0], sc[2 * s + 1][1], h2, l2u);
            split2(sc[2 * s + 1][2], sc[2 * s + 1][3], h3, l3);
            const int idx = ((qb * 4 + ks2) * 32 + lane) * 4;
            *(uint4*)&smu[AP + idx] = make_uint4(h0, h1, h2, h3);
            *(uint4*)&smu[APL + idx] = make_uint4(l0, l1u, l2u, l3);
        }
        __syncthreads();  // P + pls visible

        l1 = l1 * c1 + plsF[r1] + plsF[64 + r1];
        l2 = l2 * c2 + plsF[r2] + plsF[64 + r2];

#pragma unroll
        for (int nt = 0; nt < 8; nt++) {
            o[nt][0] *= c1; o[nt][1] *= c1; o[nt][2] *= c2; o[nt][3] *= c2;
        }

        // PV: A = P frags, B = pre-split V frags (uint2 per (ks2,nt))
#pragma unroll
        for (int ks2 = 0; ks2 < 4; ks2++) {
            const int idx = ((qb * 4 + ks2) * 32 + lane) * 4;
            uint4 phv = *(const uint4*)&smu[AP + idx];
            uint4 plv = *(const uint4*)&smu[APL + idx];
            uint32_t ph[4] = {phv.x, phv.y, phv.z, phv.w};
            uint32_t pl[4] = {plv.x, plv.y, plv.z, plv.w};
#pragma unroll
            for (int nt = 0; nt < 8; nt++) {
                const int vi = ((ks2 * 16 + dh * 8 + nt) * 32 + lane) * 2;
                uint2 vh = *(const uint2*)&smu[AV + vi];
                uint2 vl = *(const uint2*)&smu[AVL + vi];
                mma_bf16_16x8x16(o[nt], ph, vh.x, vh.y);
                mma_bf16_16x8x16(o[nt], ph, vl.x, vl.y);
                mma_bf16_16x8x16(o[nt], pl, vh.x, vh.y);
            }
        }
    }

    // Epilogue
    const float inv1 = 1.f / l1, inv2 = 1.f / l2;
    const bool dead1 = m1 < -1e8f, dead2 = m2 < -1e8f;
    const float* vm = vmean + ((size_t)b * HDIM + h) * DKDIM;
    float* O1 = Og + ((size_t)b * SDIM + q0 + r1) * DDIM + h * DKDIM;
    float* O2 = Og + ((size_t)b * SDIM + q0 + r2) * DDIM + h * DKDIM;
#pragma unroll
    for (int nt = 0; nt < 8; nt++) {
        const int d = dh * 64 + nt * 8 + tig * 2;
        float2 u1 = dead1 ? make_float2(vm[d], vm[d + 1])
                          : make_float2(o[nt][0] * inv1, o[nt][1] * inv1);
        float2 u2 = dead2 ? make_float2(vm[d], vm[d + 1])
                          : make_float2(o[nt][2] * inv2, o[nt][3] * inv2);
        *(float2*)(O1 + d) = u1;
        *(float2*)(O2 + d) = u2;
    }
}

// ---------------------------------------------------------------------------
extern "C" void kernel_launch(void* const* d_in, const int* in_sizes, int n_in,
                              void* d_out, int out_size)
{
    const float* x    = (const float*)d_in[0];
    const int*   mask = (const int*)d_in[1];
    const float* wq   = (const float*)d_in[2];
    const float* wk   = (const float*)d_in[3];
    const float* wv   = (const float*)d_in[4];
    const float* wo   = (const float*)d_in[5];
    float* out = (float*)d_out;

    float *pQ, *pK, *pV, *pAtt, *pVm;
    uint32_t* pVF;
    cudaGetSymbolAddress((void**)&pQ, g_Q);
    cudaGetSymbolAddress((void**)&pK, g_K);
    cudaGetSymbolAddress((void**)&pV, g_V);
    cudaGetSymbolAddress((void**)&pVF, g_VF);
    cudaGetSymbolAddress((void**)&pAtt, g_att);
    cudaGetSymbolAddress((void**)&pVm, g_vmean);

    cudaFuncSetAttribute(attn_mma_kernel, cudaFuncAttributeMaxDynamicSharedMemorySize,
                         ATT_SMEM_BYTES);

    dim3 gg(GN / 128, MDIM / 128);  // (16, 64)
    gemm_mma_kernel<<<gg, 256>>>(x, wq, pQ, 1);   // Q -> A-frag layout
    gemm_mma_kernel<<<gg, 256>>>(x, wk, pK, 2);   // K -> B-frag layout
    gemm_mma_kernel<<<gg, 256>>>(x, wv, pV, 0);   // V fp32

    vmean_kernel<<<BDIM * HDIM, 1024>>>(pV, pVm);
    vsplit_kernel<<<dim3(HDIM, SDIM / 16, BDIM), 128>>>(pV, pVF);

    attn_mma_kernel<<<dim3(SDIM / 64, HDIM, BDIM), 256, ATT_SMEM_BYTES>>>(
        (const uint4*)pQ, (const uint4*)pK, (const uint4*)pVF, mask, pVm, pAtt);

    gemm_mma_kernel<<<gg, 256>>>(pAtt, wo, out, 0);
}